// round 2
// baseline (speedup 1.0000x reference)
#include <cuda_runtime.h>

#define NEGC -1000000000.0f
#define B_ 8
#define S_ 4096
#define D_ 256
#define PAD 136   // floats per smem row: 16B-aligned, breaks bank patterns

// Scratch (allocation-free rule: __device__ globals)
__device__ float g_s1[B_ * D_ * D_];        // [b][d][e]
__device__ float g_inva[B_ * S_];
__device__ float g_invb[B_ * S_];
__device__ float g_mul[B_ * S_];            // mask-folded: 0 or inva
__device__ float g_add[B_ * S_];            // mask-folded: NEG or 0
__device__ int   g_mask_mode;               // 0=bool(1B), 1=int32, 2=float32

// ---------------------------------------------------------------------------
// Three-way mask dtype detection, reading only the first 32768 bytes (safe
// for every candidate dtype: bool needs 32768B, int32/float need 131072B).
//  - any byte >= 2           -> float32 (1.0f = 00 00 80 3F)
//  - else any u32 not in {0,1} -> bool  (packed flags, e.g. 0x00010001)
//  - else                    -> int32  (words exactly 0 or 1)
// ---------------------------------------------------------------------------
__global__ void detect_mask_kernel(const unsigned int* __restrict__ m) {
    __shared__ int s_big, s_odd;
    if (threadIdx.x == 0) { s_big = 0; s_odd = 0; }
    __syncthreads();
    int big = 0, odd = 0;
    for (int i = threadIdx.x; i < (B_ * S_) / 4; i += blockDim.x) {
        unsigned int w = m[i];
        // any byte >= 2 ?
        unsigned int b0 = w & 0xFFu, b1 = (w >> 8) & 0xFFu,
                     b2 = (w >> 16) & 0xFFu, b3 = (w >> 24) & 0xFFu;
        if (b0 > 1u || b1 > 1u || b2 > 1u || b3 > 1u) big = 1;
        if (w != 0u && w != 1u) odd = 1;
    }
    if (big) s_big = 1;
    if (odd) s_odd = 1;
    __syncthreads();
    if (threadIdx.x == 0)
        g_mask_mode = s_big ? 2 : (s_odd ? 0 : 1);
}

// ---------------------------------------------------------------------------
// Row norms: inva = 1/sum(q^2), invb = 1/sum(k^2). One warp per row.
// ---------------------------------------------------------------------------
__global__ void rownorm_kernel(const float4* __restrict__ q,
                               const float4* __restrict__ k) {
    int row  = blockIdx.x * 8 + (threadIdx.x >> 5);   // 8 warps/block
    int lane = threadIdx.x & 31;
    const float4* qr = q + (size_t)row * (D_ / 4);
    const float4* kr = k + (size_t)row * (D_ / 4);
    float sq = 0.f, sk = 0.f;
#pragma unroll
    for (int i = 0; i < 2; i++) {
        float4 v = qr[lane + i * 32];
        sq += v.x * v.x + v.y * v.y + v.z * v.z + v.w * v.w;
        v = kr[lane + i * 32];
        sk += v.x * v.x + v.y * v.y + v.z * v.z + v.w * v.w;
    }
#pragma unroll
    for (int o = 16; o; o >>= 1) {
        sq += __shfl_xor_sync(0xFFFFFFFFu, sq, o);
        sk += __shfl_xor_sync(0xFFFFFFFFu, sk, o);
    }
    if (lane == 0) {
        g_inva[row] = 1.0f / sq;
        g_invb[row] = 1.0f / sk;
    }
}

// ---------------------------------------------------------------------------
// Fold mask + inva into per-row (mul, add).
// ---------------------------------------------------------------------------
__global__ void mask_prep_kernel(const void* __restrict__ m) {
    int i = blockIdx.x * blockDim.x + threadIdx.x;   // B_*S_ threads
    int mode = g_mask_mode;
    bool mk;
    if (mode == 2)      mk = (reinterpret_cast<const float*>(m)[i] != 0.0f);
    else if (mode == 1) mk = (reinterpret_cast<const int*>(m)[i] != 0);
    else                mk = (reinterpret_cast<const unsigned char*>(m)[i] != 0);
    g_mul[i] = mk ? 0.0f : g_inva[i];
    g_add[i] = mk ? NEGC : 0.0f;
}

// ---------------------------------------------------------------------------
// Zero s1 scratch (needed every graph replay: s1 built via atomics).
// ---------------------------------------------------------------------------
__global__ void zero_s1_kernel() {
    int i = blockIdx.x * blockDim.x + threadIdx.x;
    reinterpret_cast<float4*>(g_s1)[i] = make_float4(0.f, 0.f, 0.f, 0.f);
}

// ---------------------------------------------------------------------------
// s1[b,d,e] += sum_s (K[b,s,d]*invb[b,s]) * V[b,s,e]
// 128x128 output tile / CTA, 256 threads, 8x8 per-thread microtile,
// split-S (16 ways) with atomicAdd reduction into g_s1.
// grid = (4 tiles, 16 splits, B)
// ---------------------------------------------------------------------------
__global__ __launch_bounds__(256) void s1_kernel(const float* __restrict__ K,
                                                 const float* __restrict__ V) {
    __shared__ float Ks[16][PAD];
    __shared__ float Vs[16][PAD];

    const int b  = blockIdx.z;
    const int dt = (blockIdx.x >> 1) * 128;
    const int et = (blockIdx.x & 1) * 128;
    const int s0 = blockIdx.y * (S_ / 16);      // 256 rows per split
    const int tid = threadIdx.x;
    const int tx = tid & 15, ty = tid >> 4;

    const float* Kb   = K + (size_t)b * S_ * D_;
    const float* Vb   = V + (size_t)b * S_ * D_;
    const float* invb = g_invb + b * S_;

    float acc[8][8];
#pragma unroll
    for (int i = 0; i < 8; i++)
#pragma unroll
        for (int j = 0; j < 8; j++) acc[i][j] = 0.f;

    for (int ss = 0; ss < S_ / 16; ss += 16) {
#pragma unroll
        for (int t = 0; t < 2; t++) {
            int idx = tid * 2 + t;          // 0..511
            int r = idx >> 5;               // 16 rows
            int c = idx & 31;               // 32 float4 per row
            int s = s0 + ss + r;
            float ib = invb[s];
            float4 kv = *reinterpret_cast<const float4*>(Kb + (size_t)s * D_ + dt + c * 4);
            float4 vv = *reinterpret_cast<const float4*>(Vb + (size_t)s * D_ + et + c * 4);
            kv.x *= ib; kv.y *= ib; kv.z *= ib; kv.w *= ib;
            *reinterpret_cast<float4*>(&Ks[r][c * 4]) = kv;
            *reinterpret_cast<float4*>(&Vs[r][c * 4]) = vv;
        }
        __syncthreads();

#pragma unroll
        for (int kk = 0; kk < 16; kk++) {
            float4 a0 = *reinterpret_cast<float4*>(&Ks[kk][ty * 4]);
            float4 a1 = *reinterpret_cast<float4*>(&Ks[kk][64 + ty * 4]);
            float4 b0 = *reinterpret_cast<float4*>(&Vs[kk][tx * 4]);
            float4 b1 = *reinterpret_cast<float4*>(&Vs[kk][64 + tx * 4]);
            float af[8] = {a0.x, a0.y, a0.z, a0.w, a1.x, a1.y, a1.z, a1.w};
            float bf[8] = {b0.x, b0.y, b0.z, b0.w, b1.x, b1.y, b1.z, b1.w};
#pragma unroll
            for (int i = 0; i < 8; i++)
#pragma unroll
                for (int j = 0; j < 8; j++) acc[i][j] += af[i] * bf[j];
        }
        __syncthreads();
    }

    float* s1b = g_s1 + (size_t)b * D_ * D_;
#pragma unroll
    for (int i = 0; i < 8; i++) {
        int drow = dt + ((i < 4) ? (ty * 4 + i) : (64 + ty * 4 + i - 4));
#pragma unroll
        for (int j = 0; j < 8; j++) {
            int ecol = et + ((j < 4) ? (tx * 4 + j) : (64 + tx * 4 + j - 4));
            atomicAdd(&s1b[drow * D_ + ecol], acc[i][j]);
        }
    }
}

// ---------------------------------------------------------------------------
// out[b,s,e] = (1/256) * sum_d score[b,s,d] * s1[b,d,e]
// score[s,d] = Q[s,d]*mul[s] + add[s]   (mask folded into mul/add)
// 128(s) x 128(e) tile / CTA. grid = (2 col tiles, 32 row tiles, B)
// ---------------------------------------------------------------------------
__global__ __launch_bounds__(256) void s2_kernel(const float* __restrict__ Q,
                                                 float* __restrict__ out) {
    __shared__ float Qs[16][PAD];    // transposed: [d_local][s_local]
    __shared__ float S1s[16][PAD];
    __shared__ float mul_s[128];
    __shared__ float add_s[128];

    const int b  = blockIdx.z;
    const int et = blockIdx.x * 128;
    const int st = blockIdx.y * 128;
    const int tid = threadIdx.x;
    const int tx = tid & 15, ty = tid >> 4;

    if (tid < 128) {
        mul_s[tid] = g_mul[b * S_ + st + tid];
        add_s[tid] = g_add[b * S_ + st + tid];
    }
    __syncthreads();

    const float* Qb  = Q + (size_t)b * S_ * D_;
    const float* s1b = g_s1 + (size_t)b * D_ * D_;

    float acc[8][8];
#pragma unroll
    for (int i = 0; i < 8; i++)
#pragma unroll
        for (int j = 0; j < 8; j++) acc[i][j] = 0.f;

    for (int d0 = 0; d0 < D_; d0 += 16) {
#pragma unroll
        for (int t = 0; t < 2; t++) {
            int idx = tid * 2 + t;      // 0..511
            int r = idx >> 2;           // s row 0..127
            int c = idx & 3;            // float4 index within 16 d-values
            float4 qv = *reinterpret_cast<const float4*>(Qb + (size_t)(st + r) * D_ + d0 + c * 4);
            float m = mul_s[r], ad = add_s[r];
            Qs[c * 4 + 0][r] = qv.x * m + ad;
            Qs[c * 4 + 1][r] = qv.y * m + ad;
            Qs[c * 4 + 2][r] = qv.z * m + ad;
            Qs[c * 4 + 3][r] = qv.w * m + ad;
        }
#pragma unroll
        for (int t = 0; t < 2; t++) {
            int idx = tid * 2 + t;
            int r = idx >> 5;
            int c = idx & 31;
            *reinterpret_cast<float4*>(&S1s[r][c * 4]) =
                *reinterpret_cast<const float4*>(s1b + (size_t)(d0 + r) * D_ + et + c * 4);
        }
        __syncthreads();

#pragma unroll
        for (int kk = 0; kk < 16; kk++) {
            float4 a0 = *reinterpret_cast<float4*>(&Qs[kk][ty * 4]);
            float4 a1 = *reinterpret_cast<float4*>(&Qs[kk][64 + ty * 4]);
            float4 b0 = *reinterpret_cast<float4*>(&S1s[kk][tx * 4]);
            float4 b1 = *reinterpret_cast<float4*>(&S1s[kk][64 + tx * 4]);
            float af[8] = {a0.x, a0.y, a0.z, a0.w, a1.x, a1.y, a1.z, a1.w};
            float bf[8] = {b0.x, b0.y, b0.z, b0.w, b1.x, b1.y, b1.z, b1.w};
#pragma unroll
            for (int i = 0; i < 8; i++)
#pragma unroll
                for (int j = 0; j < 8; j++) acc[i][j] += af[i] * bf[j];
        }
        __syncthreads();
    }

    float* ob = out + (size_t)b * S_ * D_;
    const float inv_d = 1.0f / 256.0f;
#pragma unroll
    for (int i = 0; i < 8; i++) {
        int srow = st + ((i < 4) ? (ty * 4 + i) : (64 + ty * 4 + i - 4));
        float4 o0 = make_float4(acc[i][0] * inv_d, acc[i][1] * inv_d,
                                acc[i][2] * inv_d, acc[i][3] * inv_d);
        float4 o1 = make_float4(acc[i][4] * inv_d, acc[i][5] * inv_d,
                                acc[i][6] * inv_d, acc[i][7] * inv_d);
        *reinterpret_cast<float4*>(ob + (size_t)srow * D_ + et + tx * 4)      = o0;
        *reinterpret_cast<float4*>(ob + (size_t)srow * D_ + et + 64 + tx * 4) = o1;
    }
}

// ---------------------------------------------------------------------------
extern "C" void kernel_launch(void* const* d_in, const int* in_sizes, int n_in,
                              void* d_out, int out_size) {
    const float* Q = reinterpret_cast<const float*>(d_in[0]);
    const float* K = reinterpret_cast<const float*>(d_in[1]);
    const float* V = reinterpret_cast<const float*>(d_in[2]);
    const void*  M = d_in[3];
    float* out = reinterpret_cast<float*>(d_out);

    detect_mask_kernel<<<1, 256>>>(reinterpret_cast<const unsigned int*>(M));
    rownorm_kernel<<<(B_ * S_) / 8, 256>>>(reinterpret_cast<const float4*>(Q),
                                           reinterpret_cast<const float4*>(K));
    mask_prep_kernel<<<(B_ * S_) / 256, 256>>>(M);
    zero_s1_kernel<<<(B_ * D_ * D_) / (4 * 256), 256>>>();
    {
        dim3 g(4, 16, B_);
        s1_kernel<<<g, 256>>>(K, V);
    }
    {
        dim3 g(2, S_ / 128, B_);
        s2_kernel<<<g, 256>>>(Q, out);
    }
}

// round 4
// speedup vs baseline: 1.5575x; 1.5575x over previous
#include <cuda_runtime.h>
#include <cuda_bf16.h>
#include <mma.h>
#include <cstdint>

using namespace nvcuda;

#define NEGC -1000000000.0f
#define B_ 8
#define S_ 4096
#define D_ 256

// ---------------------------------------------------------------------------
// Scratch (__device__ globals; no allocation allowed)
// ---------------------------------------------------------------------------
__device__ __nv_bfloat16 g_Kt[B_ * D_ * S_];   // [b][d][s]  K^T * invb
__device__ __nv_bfloat16 g_Vt[B_ * D_ * S_];   // [b][e][s]  V^T
__device__ __nv_bfloat16 g_Qc[B_ * S_ * D_];   // [b][s][d]  Q * mul (masked rows = 0)
__device__ float         g_s1f[B_ * D_ * D_];  // [b][d][e]  fp32 accum
__device__ __nv_bfloat16 g_s1t[B_ * D_ * D_];  // [b][e][d]  bf16 transposed
__device__ float         g_t[B_ * D_];         // [b][e] exact fp32 colsum for masked rows
__device__ float g_inva[B_ * S_];
__device__ float g_invb[B_ * S_];
__device__ float g_c[B_ * S_];                 // rowsum_d(K) * invb
__device__ float g_mul[B_ * S_];
__device__ float g_add[B_ * S_];               // NEG if masked else 0
__device__ int   g_mask_mode;

// ---------------------------------------------------------------------------
// Mask dtype detection (bool bytes / int32 / float32)
// ---------------------------------------------------------------------------
__global__ void detect_mask_kernel(const unsigned int* __restrict__ m) {
    __shared__ int s_big, s_odd;
    if (threadIdx.x == 0) { s_big = 0; s_odd = 0; }
    __syncthreads();
    int big = 0, odd = 0;
    for (int i = threadIdx.x; i < (B_ * S_) / 4; i += blockDim.x) {
        unsigned int w = m[i];
        unsigned int b0 = w & 0xFFu, b1 = (w >> 8) & 0xFFu, b2 = (w >> 16) & 0xFFu, b3 = w >> 24;
        if (b0 > 1u || b1 > 1u || b2 > 1u || b3 > 1u) big = 1;
        if (w != 0u && w != 1u) odd = 1;
    }
    if (big) s_big = 1;
    if (odd) s_odd = 1;
    __syncthreads();
    if (threadIdx.x == 0) g_mask_mode = s_big ? 2 : (s_odd ? 0 : 1);
}

// ---------------------------------------------------------------------------
// Row norms + rowsum: inva=1/Σq², invb=1/Σk², c=Σk·invb. One warp per row.
// ---------------------------------------------------------------------------
__global__ void rownorm_kernel(const float4* __restrict__ q, const float4* __restrict__ k) {
    int row  = blockIdx.x * 8 + (threadIdx.x >> 5);
    int lane = threadIdx.x & 31;
    const float4* qr = q + (size_t)row * (D_ / 4);
    const float4* kr = k + (size_t)row * (D_ / 4);
    float sq = 0.f, sk = 0.f, rk = 0.f;
#pragma unroll
    for (int i = 0; i < 2; i++) {
        float4 v = qr[lane + i * 32];
        sq += v.x * v.x + v.y * v.y + v.z * v.z + v.w * v.w;
        v = kr[lane + i * 32];
        sk += v.x * v.x + v.y * v.y + v.z * v.z + v.w * v.w;
        rk += v.x + v.y + v.z + v.w;
    }
#pragma unroll
    for (int o = 16; o; o >>= 1) {
        sq += __shfl_xor_sync(0xFFFFFFFFu, sq, o);
        sk += __shfl_xor_sync(0xFFFFFFFFu, sk, o);
        rk += __shfl_xor_sync(0xFFFFFFFFu, rk, o);
    }
    if (lane == 0) {
        float ib = 1.0f / sk;
        g_inva[row] = 1.0f / sq;
        g_invb[row] = ib;
        g_c[row]    = rk * ib;
    }
}

__global__ void mask_prep_kernel(const void* __restrict__ m) {
    int i = blockIdx.x * blockDim.x + threadIdx.x;
    int mode = g_mask_mode;
    bool mk;
    if (mode == 2)      mk = (reinterpret_cast<const float*>(m)[i] != 0.0f);
    else if (mode == 1) mk = (reinterpret_cast<const int*>(m)[i] != 0);
    else                mk = (reinterpret_cast<const unsigned char*>(m)[i] != 0);
    g_mul[i] = mk ? 0.0f : g_inva[i];
    g_add[i] = mk ? NEGC : 0.0f;
}

// Zero s1f + t (atomics re-accumulate every graph replay)
__global__ void zero_kernel() {
    int i = blockIdx.x * blockDim.x + threadIdx.x;
    int n1 = (B_ * D_ * D_) / 4;
    if (i < n1) reinterpret_cast<float4*>(g_s1f)[i] = make_float4(0.f, 0.f, 0.f, 0.f);
    else if (i < n1 + (B_ * D_) / 4)
        reinterpret_cast<float4*>(g_t)[i - n1] = make_float4(0.f, 0.f, 0.f, 0.f);
}

// ---------------------------------------------------------------------------
// Transpose+convert K,V: [b][s][d] fp32 -> [b][d][s] bf16 (K scaled by invb)
// ---------------------------------------------------------------------------
__global__ __launch_bounds__(256) void convKV_kernel(const float* __restrict__ K,
                                                     const float* __restrict__ V) {
    __shared__ float tk[32][33];
    __shared__ float tv[32][33];
    int b  = blockIdx.z;
    int s0 = blockIdx.x * 32;
    int d0 = blockIdx.y * 32;
    int tx = threadIdx.x & 31, ty = threadIdx.x >> 5;   // 32x8
    const float* Kb = K + (size_t)b * S_ * D_;
    const float* Vb = V + (size_t)b * S_ * D_;
#pragma unroll
    for (int j = 0; j < 4; j++) {
        int r = ty + j * 8;
        float ib = g_invb[b * S_ + s0 + r];
        tk[r][tx] = Kb[(size_t)(s0 + r) * D_ + d0 + tx] * ib;
        tv[r][tx] = Vb[(size_t)(s0 + r) * D_ + d0 + tx];
    }
    __syncthreads();
    __nv_bfloat16* Ko = g_Kt + (size_t)b * D_ * S_;
    __nv_bfloat16* Vo = g_Vt + (size_t)b * D_ * S_;
#pragma unroll
    for (int j = 0; j < 4; j++) {
        int r = ty + j * 8;   // d-local
        Ko[(size_t)(d0 + r) * S_ + s0 + tx] = __float2bfloat16(tk[tx][r]);
        Vo[(size_t)(d0 + r) * S_ + s0 + tx] = __float2bfloat16(tv[tx][r]);
    }
}

// Q convert: Qc = bf16(Q * mul[row])  (masked rows -> 0)
__global__ __launch_bounds__(256) void convQ_kernel(const float4* __restrict__ Q) {
    int i4 = blockIdx.x * blockDim.x + threadIdx.x;   // B*S*D/4
    int srow = i4 >> 6;                               // D/4 = 64 float4 per row
    float m = g_mul[srow];
    float4 v = Q[i4];
    __nv_bfloat162 h0 = __floats2bfloat162_rn(v.x * m, v.y * m);
    __nv_bfloat162 h1 = __floats2bfloat162_rn(v.z * m, v.w * m);
    uint2 o;
    o.x = *reinterpret_cast<uint32_t*>(&h0);
    o.y = *reinterpret_cast<uint32_t*>(&h1);
    reinterpret_cast<uint2*>(g_Qc)[i4] = o;
}

// ---------------------------------------------------------------------------
// Exact fp32: t[b,e] = sum_s c[b,s] * V[b,s,e].  grid (32 s-splits, B)
// ---------------------------------------------------------------------------
__global__ __launch_bounds__(256) void tgemv_kernel(const float* __restrict__ V) {
    int b  = blockIdx.y;
    int s0 = blockIdx.x * (S_ / 32);
    int e  = threadIdx.x;
    const float* Vb = V + (size_t)b * S_ * D_;
    const float* cb = g_c + b * S_;
    float acc = 0.f;
    for (int s = s0; s < s0 + S_ / 32; s++)
        acc += cb[s] * Vb[(size_t)s * D_ + e];
    atomicAdd(&g_t[b * D_ + e], acc);
}

// ---------------------------------------------------------------------------
// WMMA GEMM1: s1f[b,d,e] += sum_s Kt[b,d,s] * Vt[b,e,s]
// CTA: 128x128 tile, 256 thr = 8 warps (4 rows x 2 cols), warp = 32x64.
// A row-major [m=d][k=s], B col-major via storage [n=e][k=s].
// grid (4 tiles, 8 s-splits, B).
// ---------------------------------------------------------------------------
#define KC 64
#define SA 72   // smem stride (bf16 elems)

__global__ __launch_bounds__(256) void gemm1_kernel() {
    __shared__ __nv_bfloat16 As[128][SA];
    __shared__ __nv_bfloat16 Bs[128][SA];
    __shared__ float stage[8][16][20];

    const int tid = threadIdx.x;
    const int wid = tid >> 5;
    const int lane = tid & 31;
    const int b  = blockIdx.z;
    const int dt = (blockIdx.x >> 1) * 128;
    const int et = (blockIdx.x & 1) * 128;
    const int s0 = blockIdx.y * (S_ / 8);
    const int m0 = (wid >> 1) * 32;
    const int n0 = (wid & 1) * 64;

    const __nv_bfloat16* Abase = g_Kt + ((size_t)b * D_ + dt) * S_ + s0;
    const __nv_bfloat16* Bbase = g_Vt + ((size_t)b * D_ + et) * S_ + s0;

    wmma::fragment<wmma::accumulator, 16, 16, 16, float> acc[2][4];
#pragma unroll
    for (int i = 0; i < 2; i++)
#pragma unroll
        for (int j = 0; j < 4; j++) wmma::fill_fragment(acc[i][j], 0.0f);

    for (int ch = 0; ch < (S_ / 8) / KC; ch++) {
#pragma unroll
        for (int it = 0; it < 4; it++) {
            int ci = tid + it * 256;         // 0..1023 uint4 slots
            int row = ci >> 3;
            int c8 = ci & 7;
            *reinterpret_cast<uint4*>(&As[row][c8 * 8]) =
                *reinterpret_cast<const uint4*>(Abase + (size_t)row * S_ + ch * KC + c8 * 8);
            *reinterpret_cast<uint4*>(&Bs[row][c8 * 8]) =
                *reinterpret_cast<const uint4*>(Bbase + (size_t)row * S_ + ch * KC + c8 * 8);
        }
        __syncthreads();
#pragma unroll
        for (int kk = 0; kk < KC / 16; kk++) {
            wmma::fragment<wmma::matrix_a, 16, 16, 16, __nv_bfloat16, wmma::row_major> fa[2];
            wmma::fragment<wmma::matrix_b, 16, 16, 16, __nv_bfloat16, wmma::col_major> fb[4];
#pragma unroll
            for (int i = 0; i < 2; i++)
                wmma::load_matrix_sync(fa[i], &As[m0 + 16 * i][kk * 16], SA);
#pragma unroll
            for (int j = 0; j < 4; j++)
                wmma::load_matrix_sync(fb[j], &Bs[n0 + 16 * j][kk * 16], SA);
#pragma unroll
            for (int i = 0; i < 2; i++)
#pragma unroll
                for (int j = 0; j < 4; j++)
                    wmma::mma_sync(acc[i][j], fa[i], fb[j], acc[i][j]);
        }
        __syncthreads();
    }

    // Epilogue: atomicAdd fp32 into g_s1f via per-warp smem staging
    float* s1b = g_s1f + (size_t)b * D_ * D_;
    int r0 = lane >> 1;
    int c0 = (lane & 1) * 8;
#pragma unroll
    for (int i = 0; i < 2; i++)
#pragma unroll
        for (int j = 0; j < 4; j++) {
            wmma::store_matrix_sync(&stage[wid][0][0], acc[i][j], 20, wmma::mem_row_major);
            __syncwarp();
            int gd = dt + m0 + 16 * i + r0;
            int ge = et + n0 + 16 * j + c0;
#pragma unroll
            for (int c = 0; c < 8; c++)
                atomicAdd(&s1b[(size_t)gd * D_ + ge + c], stage[wid][r0][c0 + c]);
            __syncwarp();
        }
}

// s1 convert: s1f[b][d][e] fp32 -> s1t[b][e][d] bf16 (transposed)
__global__ __launch_bounds__(256) void s1conv_kernel() {
    __shared__ float t[32][33];
    int b  = blockIdx.z;
    int d0 = blockIdx.x * 32;
    int e0 = blockIdx.y * 32;
    int tx = threadIdx.x & 31, ty = threadIdx.x >> 5;
    const float* in = g_s1f + (size_t)b * D_ * D_;
    __nv_bfloat16* out = g_s1t + (size_t)b * D_ * D_;
#pragma unroll
    for (int j = 0; j < 4; j++) {
        int r = ty + j * 8;
        t[r][tx] = in[(size_t)(d0 + r) * D_ + e0 + tx];
    }
    __syncthreads();
#pragma unroll
    for (int j = 0; j < 4; j++) {
        int r = ty + j * 8;
        out[(size_t)(e0 + r) * D_ + d0 + tx] = __float2bfloat16(t[tx][r]);
    }
}

// ---------------------------------------------------------------------------
// WMMA GEMM2: out[b,s,e] = (1/256)*sum_d Qc[b,s,d]*s1t[b,e,d];
// masked rows -> NEG/256 * t[b,e] (exact).
// CTA: 128(s) x 128(e), grid (2 et, 32 st, B).
// ---------------------------------------------------------------------------
__global__ __launch_bounds__(256) void gemm2_kernel(float* __restrict__ out) {
    __shared__ __nv_bfloat16 As[128][SA];
    __shared__ __nv_bfloat16 Bs[128][SA];
    __shared__ float stage[8][16][20];
    __shared__ float ts[128];

    const int tid = threadIdx.x;
    const int wid = tid >> 5;
    const int lane = tid & 31;
    const int b  = blockIdx.z;
    const int et = blockIdx.x * 128;
    const int st = blockIdx.y * 128;
    const int m0 = (wid >> 1) * 32;
    const int n0 = (wid & 1) * 64;

    if (tid < 128) ts[tid] = g_t[b * D_ + et + tid];

    const __nv_bfloat16* Abase = g_Qc + ((size_t)b * S_ + st) * D_;
    const __nv_bfloat16* Bbase = g_s1t + ((size_t)b * D_ + et) * D_;

    wmma::fragment<wmma::accumulator, 16, 16, 16, float> acc[2][4];
#pragma unroll
    for (int i = 0; i < 2; i++)
#pragma unroll
        for (int j = 0; j < 4; j++) wmma::fill_fragment(acc[i][j], 0.0f);

    for (int ch = 0; ch < D_ / KC; ch++) {
#pragma unroll
        for (int it = 0; it < 4; it++) {
            int ci = tid + it * 256;
            int row = ci >> 3;
            int c8 = ci & 7;
            *reinterpret_cast<uint4*>(&As[row][c8 * 8]) =
                *reinterpret_cast<const uint4*>(Abase + (size_t)row * D_ + ch * KC + c8 * 8);
            *reinterpret_cast<uint4*>(&Bs[row][c8 * 8]) =
                *reinterpret_cast<const uint4*>(Bbase + (size_t)row * D_ + ch * KC + c8 * 8);
        }
        __syncthreads();
#pragma unroll
        for (int kk = 0; kk < KC / 16; kk++) {
            wmma::fragment<wmma::matrix_a, 16, 16, 16, __nv_bfloat16, wmma::row_major> fa[2];
            wmma::fragment<wmma::matrix_b, 16, 16, 16, __nv_bfloat16, wmma::col_major> fb[4];
#pragma unroll
            for (int i = 0; i < 2; i++)
                wmma::load_matrix_sync(fa[i], &As[m0 + 16 * i][kk * 16], SA);
#pragma unroll
            for (int j = 0; j < 4; j++)
                wmma::load_matrix_sync(fb[j], &Bs[n0 + 16 * j][kk * 16], SA);
#pragma unroll
            for (int i = 0; i < 2; i++)
#pragma unroll
                for (int j = 0; j < 4; j++)
                    wmma::mma_sync(acc[i][j], fa[i], fb[j], acc[i][j]);
        }
        __syncthreads();
    }

    // Epilogue with exact masked-row override
    const float inv_d = 1.0f / 256.0f;
    const float mc = NEGC * inv_d;
    float* ob = out + (size_t)b * S_ * D_;
    int r0 = lane >> 1;
    int c0 = (lane & 1) * 8;
#pragma unroll
    for (int i = 0; i < 2; i++) {
        int gs = st + m0 + 16 * i + r0;
        bool masked = (g_add[b * S_ + gs] != 0.0f);
#pragma unroll
        for (int j = 0; j < 4; j++) {
            wmma::store_matrix_sync(&stage[wid][0][0], acc[i][j], 20, wmma::mem_row_major);
            __syncwarp();
            int ge = et + n0 + 16 * j + c0;
            float4 v0, v1;
            if (masked) {
                v0 = make_float4(mc * ts[ge - et + 0], mc * ts[ge - et + 1],
                                 mc * ts[ge - et + 2], mc * ts[ge - et + 3]);
                v1 = make_float4(mc * ts[ge - et + 4], mc * ts[ge - et + 5],
                                 mc * ts[ge - et + 6], mc * ts[ge - et + 7]);
            } else {
                v0 = make_float4(stage[wid][r0][c0 + 0] * inv_d, stage[wid][r0][c0 + 1] * inv_d,
                                 stage[wid][r0][c0 + 2] * inv_d, stage[wid][r0][c0 + 3] * inv_d);
                v1 = make_float4(stage[wid][r0][c0 + 4] * inv_d, stage[wid][r0][c0 + 5] * inv_d,
                                 stage[wid][r0][c0 + 6] * inv_d, stage[wid][r0][c0 + 7] * inv_d);
            }
            *reinterpret_cast<float4*>(ob + (size_t)gs * D_ + ge)     = v0;
            *reinterpret_cast<float4*>(ob + (size_t)gs * D_ + ge + 4) = v1;
            __syncwarp();
        }
    }
}

// ---------------------------------------------------------------------------
extern "C" void kernel_launch(void* const* d_in, const int* in_sizes, int n_in,
                              void* d_out, int out_size) {
    const float* Q = reinterpret_cast<const float*>(d_in[0]);
    const float* K = reinterpret_cast<const float*>(d_in[1]);
    const float* V = reinterpret_cast<const float*>(d_in[2]);
    const void*  M = d_in[3];
    float* out = reinterpret_cast<float*>(d_out);

    detect_mask_kernel<<<1, 256>>>(reinterpret_cast<const unsigned int*>(M));
    rownorm_kernel<<<(B_ * S_) / 8, 256>>>(reinterpret_cast<const float4*>(Q),
                                           reinterpret_cast<const float4*>(K));
    mask_prep_kernel<<<(B_ * S_) / 256, 256>>>(M);
    zero_kernel<<<((B_ * D_ * D_ + B_ * D_) / 4 + 255) / 256, 256>>>();
    {
        dim3 g(S_ / 32, D_ / 32, B_);
        convKV_kernel<<<g, 256>>>(K, V);
    }
    convQ_kernel<<<(B_ * S_ * D_) / (4 * 256), 256>>>(reinterpret_cast<const float4*>(Q));
    {
        dim3 g(32, B_);
        tgemv_kernel<<<g, 256>>>(V);
    }
    {
        dim3 g(4, 8, B_);
        gemm1_kernel<<<g, 256>>>();
    }
    {
        dim3 g(D_ / 32, D_ / 32, B_);
        s1conv_kernel<<<g, 256>>>();
    }
    {
        dim3 g(2, S_ / 128, B_);
        gemm2_kernel<<<g, 256>>>(out);
    }
}

// round 5
// speedup vs baseline: 1.9430x; 1.2476x over previous
#include <cuda_runtime.h>
#include <cuda_bf16.h>
#include <mma.h>
#include <cstdint>

using namespace nvcuda;

#define NEGC -1000000000.0f
#define B_ 8
#define S_ 4096
#define D_ 256
#define KC 64

// ---------------------------------------------------------------------------
// Scratch (__device__ globals; no allocation allowed)
// ---------------------------------------------------------------------------
__device__ __nv_bfloat16 g_Kc[B_ * S_ * D_];   // [b][s][d]  K * invb, bf16
__device__ __nv_bfloat16 g_Vc[B_ * S_ * D_];   // [b][s][e]  V, bf16
__device__ __nv_bfloat16 g_Qc[B_ * S_ * D_];   // [b][s][d]  Q / sumsq (masked rows = 0)
__device__ float         g_s1f[B_ * D_ * D_];  // [b][d][e]  fp32 accum
__device__ __nv_bfloat16 g_s1c[B_ * D_ * D_];  // [b][d][e]  bf16
__device__ float         g_t[B_ * D_];         // exact fp32 colsum for masked rows
__device__ unsigned char g_msk[B_ * S_];
__device__ int           g_mask_mode;          // 0=bool bytes, 1=int32, 2=float32

// ---------------------------------------------------------------------------
// Helpers
// ---------------------------------------------------------------------------
__device__ __forceinline__ void cp16(void* smem_dst, const void* gsrc) {
    uint32_t a = (uint32_t)__cvta_generic_to_shared(smem_dst);
    asm volatile("cp.async.cg.shared.global [%0], [%1], 16;" :: "r"(a), "l"(gsrc));
}
__device__ __forceinline__ void cp_commit() { asm volatile("cp.async.commit_group;"); }
#define CP_WAIT(N) asm volatile("cp.async.wait_group %0;" :: "n"(N))

__device__ __forceinline__ uint4 pack8(float4 a, float4 b, float m) {
    __nv_bfloat162 h0 = __floats2bfloat162_rn(a.x * m, a.y * m);
    __nv_bfloat162 h1 = __floats2bfloat162_rn(a.z * m, a.w * m);
    __nv_bfloat162 h2 = __floats2bfloat162_rn(b.x * m, b.y * m);
    __nv_bfloat162 h3 = __floats2bfloat162_rn(b.z * m, b.w * m);
    uint4 o;
    o.x = *reinterpret_cast<uint32_t*>(&h0);
    o.y = *reinterpret_cast<uint32_t*>(&h1);
    o.z = *reinterpret_cast<uint32_t*>(&h2);
    o.w = *reinterpret_cast<uint32_t*>(&h3);
    return o;
}

// ---------------------------------------------------------------------------
// Fused zero + mask-dtype detect.  blocks 0..511 zero s1f, 512 zeros t,
// 513 detects mask dtype.
// ---------------------------------------------------------------------------
__global__ void zero_detect_kernel(const unsigned int* __restrict__ m) {
    int bx = blockIdx.x;
    if (bx < 512) {
        reinterpret_cast<float4*>(g_s1f)[bx * 256 + threadIdx.x] =
            make_float4(0.f, 0.f, 0.f, 0.f);
    } else if (bx == 512) {
        reinterpret_cast<float4*>(g_t)[threadIdx.x] = make_float4(0.f, 0.f, 0.f, 0.f);
        reinterpret_cast<float4*>(g_t)[threadIdx.x + 256] = make_float4(0.f, 0.f, 0.f, 0.f);
    } else {
        __shared__ int s_big, s_odd;
        if (threadIdx.x == 0) { s_big = 0; s_odd = 0; }
        __syncthreads();
        int big = 0, odd = 0;
        for (int i = threadIdx.x; i < (B_ * S_) / 4; i += blockDim.x) {
            unsigned int w = m[i];
            unsigned int b0 = w & 0xFFu, b1 = (w >> 8) & 0xFFu,
                         b2 = (w >> 16) & 0xFFu, b3 = w >> 24;
            if (b0 > 1u || b1 > 1u || b2 > 1u || b3 > 1u) big = 1;
            if (w != 0u && w != 1u) odd = 1;
        }
        if (big) s_big = 1;
        if (odd) s_odd = 1;
        __syncthreads();
        if (threadIdx.x == 0) g_mask_mode = s_big ? 2 : (s_odd ? 0 : 1);
    }
}

// ---------------------------------------------------------------------------
// prepKV: one pass over K,V.  Per CTA: 32 s-rows.  Computes invb per row,
// writes Kc = bf16(K*invb), Vc = bf16(V), accumulates t[b,e] += c[s]*V[s,e]
// (c = rowsum(K)*invb) exactly in fp32.
// grid (S/32, B), 256 threads (8 warps x 4 rows).
// ---------------------------------------------------------------------------
__global__ __launch_bounds__(256) void prepKV_kernel(const float* __restrict__ K,
                                                     const float* __restrict__ V) {
    __shared__ float Vsm[32][264];
    __shared__ float csm[32];
    const int b = blockIdx.y, s0 = blockIdx.x * 32;
    const int tid = threadIdx.x, wid = tid >> 5, lane = tid & 31;
    const size_t base = ((size_t)b * S_ + s0) * D_;

#pragma unroll
    for (int i = 0; i < 4; i++) {
        int r = wid * 4 + i;
        const float4* kr = reinterpret_cast<const float4*>(K + base + (size_t)r * D_) + lane * 2;
        float4 k0 = kr[0], k1 = kr[1];
        float sk = k0.x * k0.x + k0.y * k0.y + k0.z * k0.z + k0.w * k0.w
                 + k1.x * k1.x + k1.y * k1.y + k1.z * k1.z + k1.w * k1.w;
        float rk = k0.x + k0.y + k0.z + k0.w + k1.x + k1.y + k1.z + k1.w;
#pragma unroll
        for (int o = 16; o; o >>= 1) {
            sk += __shfl_xor_sync(0xFFFFFFFFu, sk, o);
            rk += __shfl_xor_sync(0xFFFFFFFFu, rk, o);
        }
        float ib = 1.0f / sk;
        reinterpret_cast<uint4*>(g_Kc)[(base + (size_t)r * D_) / 8 + lane] = pack8(k0, k1, ib);

        const float4* vr = reinterpret_cast<const float4*>(V + base + (size_t)r * D_) + lane * 2;
        float4 v0 = vr[0], v1 = vr[1];
        *reinterpret_cast<float4*>(&Vsm[r][lane * 8])     = v0;
        *reinterpret_cast<float4*>(&Vsm[r][lane * 8 + 4]) = v1;
        reinterpret_cast<uint4*>(g_Vc)[(base + (size_t)r * D_) / 8 + lane] = pack8(v0, v1, 1.0f);
        if (lane == 0) csm[r] = rk * ib;
    }
    __syncthreads();

    float acc = 0.f;
    int e = tid;
#pragma unroll 8
    for (int s = 0; s < 32; s++) acc += csm[s] * Vsm[s][e];
    atomicAdd(&g_t[b * D_ + e], acc);
}

// ---------------------------------------------------------------------------
// prepQ: one pass over Q.  Qc = bf16(Q/sumsq), masked rows -> 0; mask byte out.
// ---------------------------------------------------------------------------
__global__ __launch_bounds__(256) void prepQ_kernel(const float* __restrict__ Q,
                                                    const void* __restrict__ m) {
    const int b = blockIdx.y, s0 = blockIdx.x * 32;
    const int tid = threadIdx.x, wid = tid >> 5, lane = tid & 31;
    const size_t base = ((size_t)b * S_ + s0) * D_;
    const int mode = g_mask_mode;

#pragma unroll
    for (int i = 0; i < 4; i++) {
        int r = wid * 4 + i;
        int g = b * S_ + s0 + r;
        const float4* qr = reinterpret_cast<const float4*>(Q + base + (size_t)r * D_) + lane * 2;
        float4 q0 = qr[0], q1 = qr[1];
        float sq = q0.x * q0.x + q0.y * q0.y + q0.z * q0.z + q0.w * q0.w
                 + q1.x * q1.x + q1.y * q1.y + q1.z * q1.z + q1.w * q1.w;
#pragma unroll
        for (int o = 16; o; o >>= 1) sq += __shfl_xor_sync(0xFFFFFFFFu, sq, o);
        bool mk;
        if (mode == 2)      mk = (reinterpret_cast<const float*>(m)[g] != 0.0f);
        else if (mode == 1) mk = (reinterpret_cast<const int*>(m)[g] != 0);
        else                mk = (reinterpret_cast<const unsigned char*>(m)[g] != 0);
        float mul = mk ? 0.0f : 1.0f / sq;
        reinterpret_cast<uint4*>(g_Qc)[(base + (size_t)r * D_) / 8 + lane] = pack8(q0, q1, mul);
        if (lane == 0) g_msk[g] = mk ? 1 : 0;
    }
}

// ---------------------------------------------------------------------------
// GEMM1: s1f[b,d,e] += sum_s Kc[b,s,d] * Vc[b,s,e]
// A = Kc (col-major, [s][d] storage), B = Vc (row-major, [s][e] storage).
// CTA 128x128, 8 warps (4x2), warp 32x64. cp.async double-buffered, KC=64.
// grid (4 tiles, 8 s-splits, B). Dynamic smem 68KB.
// ---------------------------------------------------------------------------
#define AB1 8704   // 64*136 bf16 elems per buffer

__global__ __launch_bounds__(256) void gemm1_kernel() {
    extern __shared__ __nv_bfloat16 dsm[];
    __shared__ float stage[8][16][20];
    __nv_bfloat16* Asm = dsm;             // [2][64][136]
    __nv_bfloat16* Bsm = dsm + 2 * AB1;   // [2][64][136]

    const int tid = threadIdx.x, wid = tid >> 5, lane = tid & 31;
    const int b = blockIdx.z;
    const int dt = (blockIdx.x >> 1) * 128, et = (blockIdx.x & 1) * 128;
    const int s0 = blockIdx.y * (S_ / 8);
    const int m0 = (wid >> 1) * 32, n0 = (wid & 1) * 64;
    const __nv_bfloat16* Kb = g_Kc + (size_t)b * S_ * D_;
    const __nv_bfloat16* Vb = g_Vc + (size_t)b * S_ * D_;

    wmma::fragment<wmma::accumulator, 16, 16, 16, float> acc[2][4];
#pragma unroll
    for (int i = 0; i < 2; i++)
#pragma unroll
        for (int j = 0; j < 4; j++) wmma::fill_fragment(acc[i][j], 0.0f);

    auto load = [&](int ch, int bi) {
        const int ss = s0 + ch * KC;
        __nv_bfloat16* Ab = Asm + bi * AB1;
        __nv_bfloat16* Bb = Bsm + bi * AB1;
#pragma unroll
        for (int it = 0; it < 4; it++) {
            int ci = tid + it * 256;
            int row = ci >> 4, c16 = ci & 15;
            cp16(Ab + row * 136 + c16 * 8, Kb + (size_t)(ss + row) * D_ + dt + c16 * 8);
            cp16(Bb + row * 136 + c16 * 8, Vb + (size_t)(ss + row) * D_ + et + c16 * 8);
        }
    };

    load(0, 0); cp_commit();
    const int NCH = (S_ / 8) / KC;   // 8
    for (int ch = 0; ch < NCH; ch++) {
        if (ch + 1 < NCH) { load(ch + 1, (ch + 1) & 1); cp_commit(); CP_WAIT(1); }
        else CP_WAIT(0);
        __syncthreads();
        __nv_bfloat16* Ab = Asm + (ch & 1) * AB1;
        __nv_bfloat16* Bb = Bsm + (ch & 1) * AB1;
#pragma unroll
        for (int kk = 0; kk < KC / 16; kk++) {
            wmma::fragment<wmma::matrix_a, 16, 16, 16, __nv_bfloat16, wmma::col_major> fa[2];
            wmma::fragment<wmma::matrix_b, 16, 16, 16, __nv_bfloat16, wmma::row_major> fb[4];
#pragma unroll
            for (int i = 0; i < 2; i++)
                wmma::load_matrix_sync(fa[i], Ab + kk * 16 * 136 + m0 + 16 * i, 136);
#pragma unroll
            for (int j = 0; j < 4; j++)
                wmma::load_matrix_sync(fb[j], Bb + kk * 16 * 136 + n0 + 16 * j, 136);
#pragma unroll
            for (int i = 0; i < 2; i++)
#pragma unroll
                for (int j = 0; j < 4; j++)
                    wmma::mma_sync(acc[i][j], fa[i], fb[j], acc[i][j]);
        }
        __syncthreads();
    }

    float* s1b = g_s1f + (size_t)b * D_ * D_;
    int r0 = lane >> 1, c0 = (lane & 1) * 8;
#pragma unroll
    for (int i = 0; i < 2; i++)
#pragma unroll
        for (int j = 0; j < 4; j++) {
            wmma::store_matrix_sync(&stage[wid][0][0], acc[i][j], 20, wmma::mem_row_major);
            __syncwarp();
            int gd = dt + m0 + 16 * i + r0;
            int ge = et + n0 + 16 * j + c0;
#pragma unroll
            for (int c = 0; c < 8; c++)
                atomicAdd(&s1b[(size_t)gd * D_ + ge + c], stage[wid][r0][c0 + c]);
            __syncwarp();
        }
}

// s1 convert: fp32 -> bf16, same layout (no transpose needed).
__global__ void s1conv_kernel() {
    int i = blockIdx.x * 256 + threadIdx.x;   // B*D*D/4
    float4 v = reinterpret_cast<const float4*>(g_s1f)[i];
    __nv_bfloat162 h0 = __floats2bfloat162_rn(v.x, v.y);
    __nv_bfloat162 h1 = __floats2bfloat162_rn(v.z, v.w);
    uint2 o;
    o.x = *reinterpret_cast<uint32_t*>(&h0);
    o.y = *reinterpret_cast<uint32_t*>(&h1);
    reinterpret_cast<uint2*>(g_s1c)[i] = o;
}

// ---------------------------------------------------------------------------
// GEMM2: out[b,s,e] = (1/256)*sum_d Qc[b,s,d]*s1c[b,d,e];
// masked rows -> NEG/256 * t[b,e] (exact fp32).
// A = Qc row-major [s][d], B = s1c row-major [d][e]. cp.async double-buffered.
// grid (2 et, 32 st, B). Dynamic smem 70KB.
// ---------------------------------------------------------------------------
#define A2BUF 9216   // 128*72
#define B2BUF 8704   // 64*136

__global__ __launch_bounds__(256) void gemm2_kernel(float* __restrict__ out) {
    extern __shared__ __nv_bfloat16 dsm[];
    __shared__ float stage[8][16][20];
    __nv_bfloat16* Asm = dsm;                 // [2][128][72]
    __nv_bfloat16* Bsm = dsm + 2 * A2BUF;     // [2][64][136]

    const int tid = threadIdx.x, wid = tid >> 5, lane = tid & 31;
    const int b = blockIdx.z;
    const int et = blockIdx.x * 128, st = blockIdx.y * 128;
    const int m0 = (wid >> 1) * 32, n0 = (wid & 1) * 64;
    const __nv_bfloat16* Qb = g_Qc + ((size_t)b * S_ + st) * D_;
    const __nv_bfloat16* Sb = g_s1c + (size_t)b * D_ * D_;

    wmma::fragment<wmma::accumulator, 16, 16, 16, float> acc[2][4];
#pragma unroll
    for (int i = 0; i < 2; i++)
#pragma unroll
        for (int j = 0; j < 4; j++) wmma::fill_fragment(acc[i][j], 0.0f);

    auto load = [&](int ch, int bi) {
        __nv_bfloat16* Ab = Asm + bi * A2BUF;
        __nv_bfloat16* Bb = Bsm + bi * B2BUF;
#pragma unroll
        for (int it = 0; it < 4; it++) {
            int ci = tid + it * 256;
            int arow = ci >> 3, ac8 = ci & 7;
            cp16(Ab + arow * 72 + ac8 * 8, Qb + (size_t)arow * D_ + ch * KC + ac8 * 8);
            int brow = ci >> 4, bc16 = ci & 15;
            cp16(Bb + brow * 136 + bc16 * 8, Sb + (size_t)(ch * KC + brow) * D_ + et + bc16 * 8);
        }
    };

    load(0, 0); cp_commit();
    const int NCH = D_ / KC;   // 4
    for (int ch = 0; ch < NCH; ch++) {
        if (ch + 1 < NCH) { load(ch + 1, (ch + 1) & 1); cp_commit(); CP_WAIT(1); }
        else CP_WAIT(0);
        __syncthreads();
        __nv_bfloat16* Ab = Asm + (ch & 1) * A2BUF;
        __nv_bfloat16* Bb = Bsm + (ch & 1) * B2BUF;
#pragma unroll
        for (int kk = 0; kk < KC / 16; kk++) {
            wmma::fragment<wmma::matrix_a, 16, 16, 16, __nv_bfloat16, wmma::row_major> fa[2];
            wmma::fragment<wmma::matrix_b, 16, 16, 16, __nv_bfloat16, wmma::row_major> fb[4];
#pragma unroll
            for (int i = 0; i < 2; i++)
                wmma::load_matrix_sync(fa[i], Ab + (size_t)(m0 + 16 * i) * 72 + kk * 16, 72);
#pragma unroll
            for (int j = 0; j < 4; j++)
                wmma::load_matrix_sync(fb[j], Bb + kk * 16 * 136 + n0 + 16 * j, 136);
#pragma unroll
            for (int i = 0; i < 2; i++)
#pragma unroll
                for (int j = 0; j < 4; j++)
                    wmma::mma_sync(acc[i][j], fa[i], fb[j], acc[i][j]);
        }
        __syncthreads();
    }

    const float inv_d = 1.0f / 256.0f;
    const float mc = NEGC * inv_d;
    float* ob = out + (size_t)b * S_ * D_;
    const float* tb = g_t + b * D_;
    int r0 = lane >> 1, c0 = (lane & 1) * 8;
#pragma unroll
    for (int i = 0; i < 2; i++) {
        int gs = st + m0 + 16 * i + r0;
        bool masked = (g_msk[b * S_ + gs] != 0);
#pragma unroll
        for (int j = 0; j < 4; j++) {
            wmma::store_matrix_sync(&stage[wid][0][0], acc[i][j], 20, wmma::mem_row_major);
            __syncwarp();
            int ge = et + n0 + 16 * j + c0;
            float4 v0, v1;
            if (masked) {
                v0 = make_float4(mc * tb[ge + 0], mc * tb[ge + 1], mc * tb[ge + 2], mc * tb[ge + 3]);
                v1 = make_float4(mc * tb[ge + 4], mc * tb[ge + 5], mc * tb[ge + 6], mc * tb[ge + 7]);
            } else {
                v0 = make_float4(stage[wid][r0][c0 + 0] * inv_d, stage[wid][r0][c0 + 1] * inv_d,
                                 stage[wid][r0][c0 + 2] * inv_d, stage[wid][r0][c0 + 3] * inv_d);
                v1 = make_float4(stage[wid][r0][c0 + 4] * inv_d, stage[wid][r0][c0 + 5] * inv_d,
                                 stage[wid][r0][c0 + 6] * inv_d, stage[wid][r0][c0 + 7] * inv_d);
            }
            *reinterpret_cast<float4*>(ob + (size_t)gs * D_ + ge)     = v0;
            *reinterpret_cast<float4*>(ob + (size_t)gs * D_ + ge + 4) = v1;
            __syncwarp();
        }
    }
}

// ---------------------------------------------------------------------------
extern "C" void kernel_launch(void* const* d_in, const int* in_sizes, int n_in,
                              void* d_out, int out_size) {
    const float* Q = reinterpret_cast<const float*>(d_in[0]);
    const float* K = reinterpret_cast<const float*>(d_in[1]);
    const float* V = reinterpret_cast<const float*>(d_in[2]);
    const void*  M = d_in[3];
    float* out = reinterpret_cast<float*>(d_out);

    static bool attr_done = false;
    if (!attr_done) {
        cudaFuncSetAttribute(gemm1_kernel, cudaFuncAttributeMaxDynamicSharedMemorySize,
                             2 * 2 * AB1 * (int)sizeof(__nv_bfloat16));
        cudaFuncSetAttribute(gemm2_kernel, cudaFuncAttributeMaxDynamicSharedMemorySize,
                             2 * (A2BUF + B2BUF) * (int)sizeof(__nv_bfloat16));
        attr_done = true;
    }

    zero_detect_kernel<<<514, 256>>>(reinterpret_cast<const unsigned int*>(M));
    {
        dim3 g(S_ / 32, B_);
        prepKV_kernel<<<g, 256>>>(K, V);
        prepQ_kernel<<<g, 256>>>(Q, M);
    }
    {
        dim3 g(4, 8, B_);
        gemm1_kernel<<<g, 256, 2 * 2 * AB1 * sizeof(__nv_bfloat16)>>>();
    }
    s1conv_kernel<<<(B_ * D_ * D_) / (4 * 256), 256>>>();
    {
        dim3 g(2, S_ / 128, B_);
        gemm2_kernel<<<g, 256, 2 * (A2BUF + B2BUF) * sizeof(__nv_bfloat16)>>>(out);
    }
}

// round 6
// speedup vs baseline: 2.3656x; 1.2175x over previous
#include <cuda_runtime.h>
#include <cuda_bf16.h>
#include <mma.h>
#include <cstdint>

using namespace nvcuda;

#define NEGC -1000000000.0f
#define B_ 8
#define S_ 4096
#define D_ 256
#define KC 64
#define NSPLIT 8

// ---------------------------------------------------------------------------
// Scratch (__device__ globals; no allocation allowed)
// ---------------------------------------------------------------------------
__device__ __nv_bfloat16 g_Kc[B_ * S_ * D_];            // [b][s][d]  K * invb
__device__ __nv_bfloat16 g_Vc[B_ * S_ * D_];            // [b][s][e]  V
__device__ __nv_bfloat16 g_Qc[B_ * S_ * D_];            // [b][s][d]  Q/sumsq (masked=0)
__device__ float         g_s1part[NSPLIT * B_ * D_ * D_]; // per-split partials
__device__ __nv_bfloat16 g_s1c[B_ * D_ * D_];           // [b][d][e]  bf16
__device__ float         g_t[B_ * D_];                  // exact colsum (masked rows)
__device__ unsigned char g_msk[B_ * S_];
__device__ int           g_mask_mode;                   // 0=bool,1=int32,2=float32

// ---------------------------------------------------------------------------
// Helpers
// ---------------------------------------------------------------------------
__device__ __forceinline__ void cp16(void* smem_dst, const void* gsrc) {
    uint32_t a = (uint32_t)__cvta_generic_to_shared(smem_dst);
    asm volatile("cp.async.cg.shared.global [%0], [%1], 16;" :: "r"(a), "l"(gsrc));
}
__device__ __forceinline__ void cp_commit() { asm volatile("cp.async.commit_group;"); }
#define CP_WAIT(N) asm volatile("cp.async.wait_group %0;" :: "n"(N))

__device__ __forceinline__ uint4 pack8(float4 a, float4 b, float m) {
    __nv_bfloat162 h0 = __floats2bfloat162_rn(a.x * m, a.y * m);
    __nv_bfloat162 h1 = __floats2bfloat162_rn(a.z * m, a.w * m);
    __nv_bfloat162 h2 = __floats2bfloat162_rn(b.x * m, b.y * m);
    __nv_bfloat162 h3 = __floats2bfloat162_rn(b.z * m, b.w * m);
    uint4 o;
    o.x = *reinterpret_cast<uint32_t*>(&h0);
    o.y = *reinterpret_cast<uint32_t*>(&h1);
    o.z = *reinterpret_cast<uint32_t*>(&h2);
    o.w = *reinterpret_cast<uint32_t*>(&h3);
    return o;
}

// ---------------------------------------------------------------------------
// Block 0: zero g_t.  Block 1: mask dtype detect.
// ---------------------------------------------------------------------------
__global__ void zero_detect_kernel(const unsigned int* __restrict__ m) {
    if (blockIdx.x == 0) {
        reinterpret_cast<float4*>(g_t)[threadIdx.x] = make_float4(0.f, 0.f, 0.f, 0.f);
        reinterpret_cast<float4*>(g_t)[threadIdx.x + 256] = make_float4(0.f, 0.f, 0.f, 0.f);
    } else {
        __shared__ int s_big, s_odd;
        if (threadIdx.x == 0) { s_big = 0; s_odd = 0; }
        __syncthreads();
        int big = 0, odd = 0;
        for (int i = threadIdx.x; i < (B_ * S_) / 4; i += blockDim.x) {
            unsigned int w = m[i];
            unsigned int b0 = w & 0xFFu, b1 = (w >> 8) & 0xFFu,
                         b2 = (w >> 16) & 0xFFu, b3 = w >> 24;
            if (b0 > 1u || b1 > 1u || b2 > 1u || b3 > 1u) big = 1;
            if (w != 0u && w != 1u) odd = 1;
        }
        if (big) s_big = 1;
        if (odd) s_odd = 1;
        __syncthreads();
        if (threadIdx.x == 0) g_mask_mode = s_big ? 2 : (s_odd ? 0 : 1);
    }
}

// ---------------------------------------------------------------------------
// prepKV: single pass over K,V.  invb per row, Kc=bf16(K*invb), Vc=bf16(V),
// t[b,e] += rowsum(K)*invb * V[s,e]  (exact fp32, atomics over 128 CTAs/batch).
// ---------------------------------------------------------------------------
__global__ __launch_bounds__(256) void prepKV_kernel(const float* __restrict__ K,
                                                     const float* __restrict__ V) {
    __shared__ float Vsm[32][264];
    __shared__ float csm[32];
    const int b = blockIdx.y, s0 = blockIdx.x * 32;
    const int tid = threadIdx.x, wid = tid >> 5, lane = tid & 31;
    const size_t base = ((size_t)b * S_ + s0) * D_;

#pragma unroll
    for (int i = 0; i < 4; i++) {
        int r = wid * 4 + i;
        const float4* kr = reinterpret_cast<const float4*>(K + base + (size_t)r * D_) + lane * 2;
        float4 k0 = kr[0], k1 = kr[1];
        float sk = k0.x * k0.x + k0.y * k0.y + k0.z * k0.z + k0.w * k0.w
                 + k1.x * k1.x + k1.y * k1.y + k1.z * k1.z + k1.w * k1.w;
        float rk = k0.x + k0.y + k0.z + k0.w + k1.x + k1.y + k1.z + k1.w;
#pragma unroll
        for (int o = 16; o; o >>= 1) {
            sk += __shfl_xor_sync(0xFFFFFFFFu, sk, o);
            rk += __shfl_xor_sync(0xFFFFFFFFu, rk, o);
        }
        float ib = 1.0f / sk;
        reinterpret_cast<uint4*>(g_Kc)[(base + (size_t)r * D_) / 8 + lane] = pack8(k0, k1, ib);

        const float4* vr = reinterpret_cast<const float4*>(V + base + (size_t)r * D_) + lane * 2;
        float4 v0 = vr[0], v1 = vr[1];
        *reinterpret_cast<float4*>(&Vsm[r][lane * 8])     = v0;
        *reinterpret_cast<float4*>(&Vsm[r][lane * 8 + 4]) = v1;
        reinterpret_cast<uint4*>(g_Vc)[(base + (size_t)r * D_) / 8 + lane] = pack8(v0, v1, 1.0f);
        if (lane == 0) csm[r] = rk * ib;
    }
    __syncthreads();

    float acc = 0.f;
    int e = tid;
#pragma unroll 8
    for (int s = 0; s < 32; s++) acc += csm[s] * Vsm[s][e];
    atomicAdd(&g_t[b * D_ + e], acc);
}

// ---------------------------------------------------------------------------
// prepQ: Qc = bf16(Q/sumsq), masked rows -> 0; mask byte.
// ---------------------------------------------------------------------------
__global__ __launch_bounds__(256) void prepQ_kernel(const float* __restrict__ Q,
                                                    const void* __restrict__ m) {
    const int b = blockIdx.y, s0 = blockIdx.x * 32;
    const int tid = threadIdx.x, wid = tid >> 5, lane = tid & 31;
    const size_t base = ((size_t)b * S_ + s0) * D_;
    const int mode = g_mask_mode;

#pragma unroll
    for (int i = 0; i < 4; i++) {
        int r = wid * 4 + i;
        int g = b * S_ + s0 + r;
        const float4* qr = reinterpret_cast<const float4*>(Q + base + (size_t)r * D_) + lane * 2;
        float4 q0 = qr[0], q1 = qr[1];
        float sq = q0.x * q0.x + q0.y * q0.y + q0.z * q0.z + q0.w * q0.w
                 + q1.x * q1.x + q1.y * q1.y + q1.z * q1.z + q1.w * q1.w;
#pragma unroll
        for (int o = 16; o; o >>= 1) sq += __shfl_xor_sync(0xFFFFFFFFu, sq, o);
        bool mk;
        if (mode == 2)      mk = (reinterpret_cast<const float*>(m)[g] != 0.0f);
        else if (mode == 1) mk = (reinterpret_cast<const int*>(m)[g] != 0);
        else                mk = (reinterpret_cast<const unsigned char*>(m)[g] != 0);
        float mul = mk ? 0.0f : 1.0f / sq;
        reinterpret_cast<uint4*>(g_Qc)[(base + (size_t)r * D_) / 8 + lane] = pack8(q0, q1, mul);
        if (lane == 0) g_msk[g] = mk ? 1 : 0;
    }
}

// ---------------------------------------------------------------------------
// GEMM1: s1part[split][b,d,e] = sum_{s in split} Kc[b,s,d] * Vc[b,s,e]
// A col-major [s][d], B row-major [s][e]. 128x128 CTA tile, 8 warps (4x2).
// cp.async double-buffered. Plain stores (no atomics).
// grid (4 tiles, NSPLIT, B).  2 CTAs/SM via launch_bounds.
// ---------------------------------------------------------------------------
#define AB1 8704   // 64*136 bf16 per buffer

__global__ __launch_bounds__(256, 2) void gemm1_kernel() {
    extern __shared__ __nv_bfloat16 dsm[];
    __shared__ float stage[8][16][20];
    __nv_bfloat16* Asm = dsm;
    __nv_bfloat16* Bsm = dsm + 2 * AB1;

    const int tid = threadIdx.x, wid = tid >> 5, lane = tid & 31;
    const int b = blockIdx.z;
    const int dt = (blockIdx.x >> 1) * 128, et = (blockIdx.x & 1) * 128;
    const int split = blockIdx.y;
    const int s0 = split * (S_ / NSPLIT);
    const int m0 = (wid >> 1) * 32, n0 = (wid & 1) * 64;
    const __nv_bfloat16* Kb = g_Kc + (size_t)b * S_ * D_;
    const __nv_bfloat16* Vb = g_Vc + (size_t)b * S_ * D_;

    wmma::fragment<wmma::accumulator, 16, 16, 16, float> acc[2][4];
#pragma unroll
    for (int i = 0; i < 2; i++)
#pragma unroll
        for (int j = 0; j < 4; j++) wmma::fill_fragment(acc[i][j], 0.0f);

    auto load = [&](int ch, int bi) {
        const int ss = s0 + ch * KC;
        __nv_bfloat16* Ab = Asm + bi * AB1;
        __nv_bfloat16* Bb = Bsm + bi * AB1;
#pragma unroll
        for (int it = 0; it < 4; it++) {
            int ci = tid + it * 256;
            int row = ci >> 4, c16 = ci & 15;
            cp16(Ab + row * 136 + c16 * 8, Kb + (size_t)(ss + row) * D_ + dt + c16 * 8);
            cp16(Bb + row * 136 + c16 * 8, Vb + (size_t)(ss + row) * D_ + et + c16 * 8);
        }
    };

    load(0, 0); cp_commit();
    const int NCH = (S_ / NSPLIT) / KC;   // 8
    for (int ch = 0; ch < NCH; ch++) {
        if (ch + 1 < NCH) { load(ch + 1, (ch + 1) & 1); cp_commit(); CP_WAIT(1); }
        else CP_WAIT(0);
        __syncthreads();
        __nv_bfloat16* Ab = Asm + (ch & 1) * AB1;
        __nv_bfloat16* Bb = Bsm + (ch & 1) * AB1;
#pragma unroll
        for (int kk = 0; kk < KC / 16; kk++) {
            wmma::fragment<wmma::matrix_a, 16, 16, 16, __nv_bfloat16, wmma::col_major> fa[2];
            wmma::fragment<wmma::matrix_b, 16, 16, 16, __nv_bfloat16, wmma::row_major> fb[4];
#pragma unroll
            for (int i = 0; i < 2; i++)
                wmma::load_matrix_sync(fa[i], Ab + kk * 16 * 136 + m0 + 16 * i, 136);
#pragma unroll
            for (int j = 0; j < 4; j++)
                wmma::load_matrix_sync(fb[j], Bb + kk * 16 * 136 + n0 + 16 * j, 136);
#pragma unroll
            for (int i = 0; i < 2; i++)
#pragma unroll
                for (int j = 0; j < 4; j++)
                    wmma::mma_sync(acc[i][j], fa[i], fb[j], acc[i][j]);
        }
        __syncthreads();
    }

    float* s1p = g_s1part + ((size_t)split * B_ + b) * D_ * D_;
    int r0 = lane >> 1, c0 = (lane & 1) * 8;
#pragma unroll
    for (int i = 0; i < 2; i++)
#pragma unroll
        for (int j = 0; j < 4; j++) {
            wmma::store_matrix_sync(&stage[wid][0][0], acc[i][j], 20, wmma::mem_row_major);
            __syncwarp();
            int gd = dt + m0 + 16 * i + r0;
            int ge = et + n0 + 16 * j + c0;
            float4 v0 = *reinterpret_cast<float4*>(&stage[wid][r0][c0]);
            float4 v1 = *reinterpret_cast<float4*>(&stage[wid][r0][c0 + 4]);
            *reinterpret_cast<float4*>(&s1p[(size_t)gd * D_ + ge])     = v0;
            *reinterpret_cast<float4*>(&s1p[(size_t)gd * D_ + ge + 4]) = v1;
            __syncwarp();
        }
}

// Reduce NSPLIT partials + convert to bf16.
__global__ void s1conv_kernel() {
    int i = blockIdx.x * 256 + threadIdx.x;   // B*D*D/4
    const int stride = (B_ * D_ * D_) / 4;
    float4 a = reinterpret_cast<const float4*>(g_s1part)[i];
#pragma unroll
    for (int sp = 1; sp < NSPLIT; sp++) {
        float4 p = reinterpret_cast<const float4*>(g_s1part)[sp * stride + i];
        a.x += p.x; a.y += p.y; a.z += p.z; a.w += p.w;
    }
    __nv_bfloat162 h0 = __floats2bfloat162_rn(a.x, a.y);
    __nv_bfloat162 h1 = __floats2bfloat162_rn(a.z, a.w);
    uint2 o;
    o.x = *reinterpret_cast<uint32_t*>(&h0);
    o.y = *reinterpret_cast<uint32_t*>(&h1);
    reinterpret_cast<uint2*>(g_s1c)[i] = o;
}

// ---------------------------------------------------------------------------
// GEMM2: out[b,s,e] = (1/256)*sum_d Qc[b,s,d]*s1c[b,d,e];
// masked rows -> NEG/256 * t[b,e] (exact fp32).
// grid (2 et, 32 st, B).  2 CTAs/SM.
// ---------------------------------------------------------------------------
#define A2BUF 9216   // 128*72
#define B2BUF 8704   // 64*136

__global__ __launch_bounds__(256, 2) void gemm2_kernel(float* __restrict__ out) {
    extern __shared__ __nv_bfloat16 dsm[];
    __shared__ float stage[8][16][20];
    __nv_bfloat16* Asm = dsm;
    __nv_bfloat16* Bsm = dsm + 2 * A2BUF;

    const int tid = threadIdx.x, wid = tid >> 5, lane = tid & 31;
    const int b = blockIdx.z;
    const int et = blockIdx.x * 128, st = blockIdx.y * 128;
    const int m0 = (wid >> 1) * 32, n0 = (wid & 1) * 64;
    const __nv_bfloat16* Qb = g_Qc + ((size_t)b * S_ + st) * D_;
    const __nv_bfloat16* Sb = g_s1c + (size_t)b * D_ * D_;

    wmma::fragment<wmma::accumulator, 16, 16, 16, float> acc[2][4];
#pragma unroll
    for (int i = 0; i < 2; i++)
#pragma unroll
        for (int j = 0; j < 4; j++) wmma::fill_fragment(acc[i][j], 0.0f);

    auto load = [&](int ch, int bi) {
        __nv_bfloat16* Ab = Asm + bi * A2BUF;
        __nv_bfloat16* Bb = Bsm + bi * B2BUF;
#pragma unroll
        for (int it = 0; it < 4; it++) {
            int ci = tid + it * 256;
            int arow = ci >> 3, ac8 = ci & 7;
            cp16(Ab + arow * 72 + ac8 * 8, Qb + (size_t)arow * D_ + ch * KC + ac8 * 8);
            int brow = ci >> 4, bc16 = ci & 15;
            cp16(Bb + brow * 136 + bc16 * 8, Sb + (size_t)(ch * KC + brow) * D_ + et + bc16 * 8);
        }
    };

    load(0, 0); cp_commit();
    const int NCH = D_ / KC;   // 4
    for (int ch = 0; ch < NCH; ch++) {
        if (ch + 1 < NCH) { load(ch + 1, (ch + 1) & 1); cp_commit(); CP_WAIT(1); }
        else CP_WAIT(0);
        __syncthreads();
        __nv_bfloat16* Ab = Asm + (ch & 1) * A2BUF;
        __nv_bfloat16* Bb = Bsm + (ch & 1) * B2BUF;
#pragma unroll
        for (int kk = 0; kk < KC / 16; kk++) {
            wmma::fragment<wmma::matrix_a, 16, 16, 16, __nv_bfloat16, wmma::row_major> fa[2];
            wmma::fragment<wmma::matrix_b, 16, 16, 16, __nv_bfloat16, wmma::row_major> fb[4];
#pragma unroll
            for (int i = 0; i < 2; i++)
                wmma::load_matrix_sync(fa[i], Ab + (size_t)(m0 + 16 * i) * 72 + kk * 16, 72);
#pragma unroll
            for (int j = 0; j < 4; j++)
                wmma::load_matrix_sync(fb[j], Bb + kk * 16 * 136 + n0 + 16 * j, 136);
#pragma unroll
            for (int i = 0; i < 2; i++)
#pragma unroll
                for (int j = 0; j < 4; j++)
                    wmma::mma_sync(acc[i][j], fa[i], fb[j], acc[i][j]);
        }
        __syncthreads();
    }

    const float inv_d = 1.0f / 256.0f;
    const float mc = NEGC * inv_d;
    float* ob = out + (size_t)b * S_ * D_;
    const float* tb = g_t + b * D_;
    int r0 = lane >> 1, c0 = (lane & 1) * 8;
#pragma unroll
    for (int i = 0; i < 2; i++) {
        int gs = st + m0 + 16 * i + r0;
        bool masked = (g_msk[b * S_ + gs] != 0);
#pragma unroll
        for (int j = 0; j < 4; j++) {
            wmma::store_matrix_sync(&stage[wid][0][0], acc[i][j], 20, wmma::mem_row_major);
            __syncwarp();
            int ge = et + n0 + 16 * j + c0;
            float4 v0, v1;
            if (masked) {
                v0 = make_float4(mc * tb[ge + 0], mc * tb[ge + 1], mc * tb[ge + 2], mc * tb[ge + 3]);
                v1 = make_float4(mc * tb[ge + 4], mc * tb[ge + 5], mc * tb[ge + 6], mc * tb[ge + 7]);
            } else {
                v0 = make_float4(stage[wid][r0][c0 + 0] * inv_d, stage[wid][r0][c0 + 1] * inv_d,
                                 stage[wid][r0][c0 + 2] * inv_d, stage[wid][r0][c0 + 3] * inv_d);
                v1 = make_float4(stage[wid][r0][c0 + 4] * inv_d, stage[wid][r0][c0 + 5] * inv_d,
                                 stage[wid][r0][c0 + 6] * inv_d, stage[wid][r0][c0 + 7] * inv_d);
            }
            *reinterpret_cast<float4*>(ob + (size_t)gs * D_ + ge)     = v0;
            *reinterpret_cast<float4*>(ob + (size_t)gs * D_ + ge + 4) = v1;
            __syncwarp();
        }
    }
}

// ---------------------------------------------------------------------------
extern "C" void kernel_launch(void* const* d_in, const int* in_sizes, int n_in,
                              void* d_out, int out_size) {
    const float* Q = reinterpret_cast<const float*>(d_in[0]);
    const float* K = reinterpret_cast<const float*>(d_in[1]);
    const float* V = reinterpret_cast<const float*>(d_in[2]);
    const void*  M = d_in[3];
    float* out = reinterpret_cast<float*>(d_out);

    cudaFuncSetAttribute(gemm1_kernel, cudaFuncAttributeMaxDynamicSharedMemorySize,
                         2 * 2 * AB1 * (int)sizeof(__nv_bfloat16));
    cudaFuncSetAttribute(gemm2_kernel, cudaFuncAttributeMaxDynamicSharedMemorySize,
                         2 * (A2BUF + B2BUF) * (int)sizeof(__nv_bfloat16));

    zero_detect_kernel<<<2, 256>>>(reinterpret_cast<const unsigned int*>(M));
    {
        dim3 g(S_ / 32, B_);
        prepKV_kernel<<<g, 256>>>(K, V);
        prepQ_kernel<<<g, 256>>>(Q, M);
    }
    {
        dim3 g(4, NSPLIT, B_);
        gemm1_kernel<<<g, 256, 2 * 2 * AB1 * sizeof(__nv_bfloat16)>>>();
    }
    s1conv_kernel<<<(B_ * D_ * D_) / (4 * 256), 256>>>();
    {
        dim3 g(2, S_ / 128, B_);
        gemm2_kernel<<<g, 256, 2 * (A2BUF + B2BUF) * sizeof(__nv_bfloat16)>>>(out);
    }
}